// round 5
// baseline (speedup 1.0000x reference)
#include <cuda_runtime.h>
#include <math.h>

// Shapes: BSZ=2, SEQ=2048, DIM=2048, N_HEADS=16, HEAD_DIM=64 (2 variants/head)
// Scratch buffers (allocation-free: __device__ globals)
__device__ float g_Q[8388608];   // [b][head2(32)][s][64]
__device__ float g_K[8388608];   // [b][head2(32)][s][64]
__device__ float g_V[8388608];   // [b][h(16)][s][128]  (v1 | v2)
__device__ float g_O[16777216];  // [var(2)][b][h][s][128]
__device__ float g_A[8388608];   // [b*s][2048]  (pre-wo activations)
__device__ float g_lam;

// ---------------------------------------------------------------------------
// SGEMM: C[r][c] = sum_k A[r][k] * W[c][k]   (M=4096, N=2048, K=2048)
// mode 0: A = g_A, store row-major into Cout (d_out)
// mode 1: store into g_Q with [b][head2][s][64] scatter
// mode 2: store into g_K likewise
// mode 3: store into g_V with [b][h][s][128] scatter
// ---------------------------------------------------------------------------
__global__ __launch_bounds__(256) void sgemm_kernel(const float* __restrict__ Ain,
                                                    const float* __restrict__ W,
                                                    float* __restrict__ Cout,
                                                    int mode)
{
    __shared__ __align__(16) float As[8][128];
    __shared__ __align__(16) float Bs[8][128];

    const float* A = (mode == 0) ? (const float*)g_A : Ain;

    int tid = threadIdx.x;
    int m0 = blockIdx.y * 128;
    int n0 = blockIdx.x * 128;
    int lm = tid >> 1;
    int lk = (tid & 1) * 4;

    const float* Ap = A + (size_t)(m0 + lm) * 2048 + lk;
    const float* Wp = W + (size_t)(n0 + lm) * 2048 + lk;

    int ty = tid >> 4, tx = tid & 15;
    float acc[8][8] = {};

    for (int k0 = 0; k0 < 2048; k0 += 8) {
        float4 av = *(const float4*)(Ap + k0);
        float4 wv = *(const float4*)(Wp + k0);
        __syncthreads();
        As[lk + 0][lm] = av.x; As[lk + 1][lm] = av.y;
        As[lk + 2][lm] = av.z; As[lk + 3][lm] = av.w;
        Bs[lk + 0][lm] = wv.x; Bs[lk + 1][lm] = wv.y;
        Bs[lk + 2][lm] = wv.z; Bs[lk + 3][lm] = wv.w;
        __syncthreads();

        #pragma unroll
        for (int kk = 0; kk < 8; kk++) {
            float4 a0 = *(const float4*)&As[kk][ty * 8];
            float4 a1 = *(const float4*)&As[kk][ty * 8 + 4];
            float4 b0 = *(const float4*)&Bs[kk][tx * 8];
            float4 b1 = *(const float4*)&Bs[kk][tx * 8 + 4];
            float a[8] = {a0.x, a0.y, a0.z, a0.w, a1.x, a1.y, a1.z, a1.w};
            float b[8] = {b0.x, b0.y, b0.z, b0.w, b1.x, b1.y, b1.z, b1.w};
            #pragma unroll
            for (int i = 0; i < 8; i++)
                #pragma unroll
                for (int j = 0; j < 8; j++)
                    acc[i][j] += a[i] * b[j];
        }
    }

    int rbase = m0 + ty * 8;
    int cbase = n0 + tx * 8;

    if (mode == 0) {
        #pragma unroll
        for (int i = 0; i < 8; i++) {
            float* cp = Cout + (size_t)(rbase + i) * 2048 + cbase;
            #pragma unroll
            for (int j = 0; j < 8; j++) cp[j] = acc[i][j];
        }
    } else if (mode == 3) {
        int bb = rbase >> 11;           // batch (rows never cross 2048 boundary)
        int h  = cbase >> 7;            // 8 cols never cross a 128 boundary
        int cc = cbase & 127;
        #pragma unroll
        for (int i = 0; i < 8; i++) {
            int s = (rbase + i) & 2047;
            float* dst = g_V + ((size_t)(bb * 16 + h) * 2048 + s) * 128 + cc;
            #pragma unroll
            for (int j = 0; j < 8; j++) dst[j] = acc[i][j];
        }
    } else {
        float* G = (mode == 1) ? g_Q : g_K;
        int bb = rbase >> 11;
        int h2 = cbase >> 6;            // 8 cols never cross a 64 boundary
        int dd = cbase & 63;
        #pragma unroll
        for (int i = 0; i < 8; i++) {
            int s = (rbase + i) & 2047;
            float* dst = G + ((size_t)(bb * 32 + h2) * 2048 + s) * 64 + dd;
            #pragma unroll
            for (int j = 0; j < 8; j++) dst[j] = acc[i][j];
        }
    }
}

// ---------------------------------------------------------------------------
// RoPE applied in-place to g_Q and g_K. One thread per (row, pair j).
// Layout rows = [b][head2][s]; pairs are (2j, 2j+1), cos/sin indexed [s][j].
// ---------------------------------------------------------------------------
__global__ __launch_bounds__(256) void rope_kernel(const float* __restrict__ cosb,
                                                   const float* __restrict__ sinb)
{
    int idx = blockIdx.x * blockDim.x + threadIdx.x;  // pair index
    const int total = 2 * 32 * 2048 * 32;             // 4,194,304
    if (idx >= total) return;
    int j = idx & 31;
    int s = (idx >> 5) & 2047;
    float c  = cosb[s * 32 + j];
    float sn = sinb[s * 32 + j];

    float2* q2 = (float2*)g_Q;
    float2* k2 = (float2*)g_K;
    float2 q = q2[idx];
    q2[idx] = make_float2(q.x * c - q.y * sn, q.x * sn + q.y * c);
    float2 k = k2[idx];
    k2[idx] = make_float2(k.x * c - k.y * sn, k.x * sn + k.y * c);
}

// ---------------------------------------------------------------------------
// lambda scalar: exp(sum lq1*lk1) - exp(sum lq2*lk2) + LAMBDA_INIT
// ---------------------------------------------------------------------------
__global__ void lam_kernel(const float* __restrict__ lq1, const float* __restrict__ lk1,
                           const float* __restrict__ lq2, const float* __restrict__ lk2)
{
    if (threadIdx.x == 0) {
        float a = 0.f, b = 0.f;
        for (int i = 0; i < 64; i++) {
            a += lq1[i] * lk1[i];
            b += lq2[i] * lk2[i];
        }
        float li = 0.8f - 0.6f * expf(-9.6f);
        g_lam = expf(a) - expf(b) + li;
    }
}

// ---------------------------------------------------------------------------
// Causal flash attention, fp32. One block = 64 queries of one (b, h, variant).
// Q/K d-major in smem; scores aliased over the K-tile buffer; V dim = 128.
// grid = (SEQ/64 = 32, 2*16*2 = 64), 256 threads.
// ---------------------------------------------------------------------------
__global__ __launch_bounds__(256) void attn_kernel()
{
    __shared__ __align__(16) float Qst[64 * 68];     // [d][i], pad 68
    __shared__ __align__(16) float KstSs[64 * 36];   // [d][j] pad 36; aliased as S[row*33+col]
    __shared__ __align__(16) float Vs[32 * 128];     // [j][c]
    __shared__ float mrow[64], lrow[64], arow[64];

    int tid = threadIdx.x;
    int unit = blockIdx.y;
    int b   = unit >> 5;
    int h   = (unit >> 1) & 15;
    int var = unit & 1;
    int q0  = blockIdx.x * 64;

    const float* Qg = g_Q + (size_t)(b * 32 + h * 2 + var) * 2048 * 64;
    const float* Kg = g_K + (size_t)(b * 32 + h * 2 + var) * 2048 * 64;
    const float* Vg = g_V + (size_t)(b * 16 + h) * 2048 * 128;
    float*       Og = g_O + (size_t)var * 8388608 + (size_t)(b * 16 + h) * 2048 * 128;

    // load Q tile transposed: Qst[d][i] = Q[q0+i][d]
    #pragma unroll
    for (int t = 0; t < 16; t++) {
        int e = tid + t * 256;
        int i = e >> 6, d = e & 63;
        Qst[d * 68 + i] = Qg[(size_t)(q0 + i) * 64 + d];
    }
    if (tid < 64) { mrow[tid] = -1e30f; lrow[tid] = 0.f; }

    int ty = tid >> 4, tx = tid & 15;   // S-phase: 4 rows x 2 cols
    int rg = tid >> 4, cg = tid & 15;   // O-phase: 4 rows x 8 cols
    int srow = tid >> 2, part = tid & 3;

    float o[4][8];
    #pragma unroll
    for (int ii = 0; ii < 4; ii++)
        #pragma unroll
        for (int c = 0; c < 8; c++) o[ii][c] = 0.f;

    int nkt = (q0 >> 5) + 2;            // key tiles covering keys <= q0+63

    for (int kt = 0; kt < nkt; kt++) {
        __syncthreads();  // previous O-phase done with KstSs/Vs

        // load K tile transposed: Kst[d][j] = K[kt*32+j][d]
        #pragma unroll
        for (int t = 0; t < 8; t++) {
            int e = tid + t * 256;
            int j = e >> 6, d = e & 63;
            KstSs[d * 36 + j] = Kg[(size_t)(kt * 32 + j) * 64 + d];
        }
        // load V tile (float4)
        #pragma unroll
        for (int t = 0; t < 4; t++) {
            int e = tid + t * 256;
            int j = e >> 5, c4 = e & 31;
            *(float4*)&Vs[j * 128 + c4 * 4] =
                *(const float4*)&Vg[(size_t)(kt * 32 + j) * 128 + c4 * 4];
        }
        __syncthreads();

        // S = Q . K^T  (each thread: 4x2 fragment)
        float acc[4][2] = {};
        #pragma unroll 16
        for (int d = 0; d < 64; d++) {
            float4 a  = *(const float4*)&Qst[d * 68 + ty * 4];
            float2 bv = *(const float2*)&KstSs[d * 36 + tx * 2];
            acc[0][0] += a.x * bv.x; acc[0][1] += a.x * bv.y;
            acc[1][0] += a.y * bv.x; acc[1][1] += a.y * bv.y;
            acc[2][0] += a.z * bv.x; acc[2][1] += a.z * bv.y;
            acc[3][0] += a.w * bv.x; acc[3][1] += a.w * bv.y;
        }
        __syncthreads();  // done reading Kst, safe to alias as S

        bool needmask = (kt * 32 + 31) > q0;
        #pragma unroll
        for (int ii = 0; ii < 4; ii++) {
            int row = ty * 4 + ii;
            #pragma unroll
            for (int jj = 0; jj < 2; jj++) {
                int col = tx * 2 + jj;
                float sv = acc[ii][jj] * 0.125f;
                if (needmask && (kt * 32 + col > q0 + row)) sv = -1e30f;
                KstSs[row * 33 + col] = sv;
            }
        }
        __syncthreads();

        // online softmax: 4 threads per row, 8 cols each
        {
            float sv[8]; float mx = -1e30f;
            #pragma unroll
            for (int k2 = 0; k2 < 8; k2++) {
                sv[k2] = KstSs[srow * 33 + part * 8 + k2];
                mx = fmaxf(mx, sv[k2]);
            }
            mx = fmaxf(mx, __shfl_xor_sync(0xffffffffu, mx, 1));
            mx = fmaxf(mx, __shfl_xor_sync(0xffffffffu, mx, 2));
            float mold = mrow[srow];
            float mnew = fmaxf(mold, mx);
            float psum = 0.f;
            #pragma unroll
            for (int k2 = 0; k2 < 8; k2++) {
                float p = __expf(sv[k2] - mnew);
                KstSs[srow * 33 + part * 8 + k2] = p;
                psum += p;
            }
            psum += __shfl_xor_sync(0xffffffffu, psum, 1);
            psum += __shfl_xor_sync(0xffffffffu, psum, 2);
            if (part == 0) {
                float al = __expf(mold - mnew);
                arow[srow] = al;
                lrow[srow] = lrow[srow] * al + psum;
                mrow[srow] = mnew;
            }
        }
        __syncthreads();

        // O = O*alpha + P . V  (each thread: 4 rows x 8 cols of 64x128)
        {
            float al[4];
            #pragma unroll
            for (int ii = 0; ii < 4; ii++) al[ii] = arow[rg * 4 + ii];
            #pragma unroll
            for (int ii = 0; ii < 4; ii++)
                #pragma unroll
                for (int c = 0; c < 8; c++) o[ii][c] *= al[ii];

            #pragma unroll 4
            for (int j = 0; j < 32; j++) {
                float4 v0 = *(const float4*)&Vs[j * 128 + cg * 8];
                float4 v1 = *(const float4*)&Vs[j * 128 + cg * 8 + 4];
                float vv[8] = {v0.x, v0.y, v0.z, v0.w, v1.x, v1.y, v1.z, v1.w};
                float pp[4];
                #pragma unroll
                for (int ii = 0; ii < 4; ii++) pp[ii] = KstSs[(rg * 4 + ii) * 33 + j];
                #pragma unroll
                for (int ii = 0; ii < 4; ii++)
                    #pragma unroll
                    for (int c = 0; c < 8; c++)
                        o[ii][c] += pp[ii] * vv[c];
            }
        }
    }

    // finalize: divide by l, store
    #pragma unroll
    for (int ii = 0; ii < 4; ii++) {
        float linv = 1.0f / lrow[rg * 4 + ii];
        float4 r0 = make_float4(o[ii][0] * linv, o[ii][1] * linv,
                                o[ii][2] * linv, o[ii][3] * linv);
        float4 r1 = make_float4(o[ii][4] * linv, o[ii][5] * linv,
                                o[ii][6] * linv, o[ii][7] * linv);
        size_t base = (size_t)(q0 + rg * 4 + ii) * 128 + cg * 8;
        *(float4*)&Og[base]     = r0;
        *(float4*)&Og[base + 4] = r1;
    }
}

// ---------------------------------------------------------------------------
// Combine: attn = (O1 - lam*O2); RMSNorm(128); * subln_w * (1-LAMBDA_INIT)
// One warp per 128-dim vector; writes GEMM-ready row-major g_A.
// ---------------------------------------------------------------------------
__global__ __launch_bounds__(256) void combine_kernel(const float* __restrict__ subw)
{
    int warp = threadIdx.x >> 5, lane = threadIdx.x & 31;
    int v = blockIdx.x * 8 + warp;        // v = (b*16+h)*2048 + s, 0..65535
    const float4* p1 = (const float4*)g_O + (size_t)v * 32;
    const float4* p2 = (const float4*)(g_O + 8388608) + (size_t)v * 32;

    float lam = g_lam;
    float4 x1 = p1[lane], x2 = p2[lane];
    float4 a = make_float4(x1.x - lam * x2.x, x1.y - lam * x2.y,
                           x1.z - lam * x2.z, x1.w - lam * x2.w);
    float ss = a.x * a.x + a.y * a.y + a.z * a.z + a.w * a.w;
    #pragma unroll
    for (int off = 16; off > 0; off >>= 1)
        ss += __shfl_xor_sync(0xffffffffu, ss, off);

    float li = 0.8f - 0.6f * expf(-9.6f);
    float sc = rsqrtf(ss * (1.0f / 128.0f) + 1e-5f) * (1.0f - li);
    float4 w = ((const float4*)subw)[lane];
    float4 out = make_float4(a.x * sc * w.x, a.y * sc * w.y,
                             a.z * sc * w.z, a.w * sc * w.w);

    int b = v >> 15;
    int h = (v >> 11) & 15;
    int s = v & 2047;
    ((float4*)(g_A + (size_t)(b * 2048 + s) * 2048 + h * 128))[lane] = out;
}

// ---------------------------------------------------------------------------
extern "C" void kernel_launch(void* const* d_in, const int* in_sizes, int n_in,
                              void* d_out, int out_size)
{
    const float* x    = (const float*)d_in[0];
    const float* wq   = (const float*)d_in[1];
    const float* wk   = (const float*)d_in[2];
    const float* wv   = (const float*)d_in[3];
    const float* wo   = (const float*)d_in[4];
    const float* lq1  = (const float*)d_in[5];
    const float* lk1  = (const float*)d_in[6];
    const float* lq2  = (const float*)d_in[7];
    const float* lk2  = (const float*)d_in[8];
    const float* subw = (const float*)d_in[9];
    const float* rc   = (const float*)d_in[10];
    const float* rs   = (const float*)d_in[11];

    dim3 gemm_grid(16, 32), gemm_blk(256);

    sgemm_kernel<<<gemm_grid, gemm_blk>>>(x, wq, nullptr, 1);          // Q
    sgemm_kernel<<<gemm_grid, gemm_blk>>>(x, wk, nullptr, 2);          // K
    sgemm_kernel<<<gemm_grid, gemm_blk>>>(x, wv, nullptr, 3);          // V
    rope_kernel<<<16384, 256>>>(rc, rs);
    lam_kernel<<<1, 32>>>(lq1, lk1, lq2, lk2);
    attn_kernel<<<dim3(32, 64), 256>>>();
    combine_kernel<<<8192, 256>>>(subw);
    sgemm_kernel<<<gemm_grid, gemm_blk>>>(nullptr, wo, (float*)d_out, 0);  // out
}

// round 11
// speedup vs baseline: 1.5695x; 1.5695x over previous
#include <cuda_runtime.h>
#include <cuda_bf16.h>
#include <math.h>
#include <stdint.h>

// Shapes: BSZ=2, SEQ=2048, DIM=2048, N_HEADS=16, HEAD_DIM=64 (2 variants/head)
// fp32 scratch
__device__ float g_Q[8388608];   // [b][head2(32)][s][64]
__device__ float g_K[8388608];   // [b][head2(32)][s][64]
__device__ float g_V[8388608];   // [b][h(16)][s][128]
__device__ float g_O[16777216];  // [var(2)][b][h][s][128]
__device__ float g_lam;

// bf16 hi/lo operand scratch for tensor-core GEMMs
__device__ __nv_bfloat16 g_xh[8388608], g_xl[8388608];   // x  [4096][2048]
__device__ __nv_bfloat16 g_Ah[8388608], g_Al[8388608];   // combine out [4096][2048]
__device__ __nv_bfloat16 g_wh0[4194304], g_wl0[4194304]; // wq
__device__ __nv_bfloat16 g_wh1[4194304], g_wl1[4194304]; // wk
__device__ __nv_bfloat16 g_wh2[4194304], g_wl2[4194304]; // wv
__device__ __nv_bfloat16 g_wh3[4194304], g_wl3[4194304]; // wo

// ---------------------------------------------------------------------------
// Helpers (all base-ISA: ldmatrix sm_75+, bf16 mma.sync sm_80+)
// ---------------------------------------------------------------------------
__device__ __forceinline__ uint32_t smem_u32(const void* p) {
    uint32_t a;
    asm("{ .reg .u64 t; cvta.to.shared.u64 t, %1; cvt.u32.u64 %0, t; }" : "=r"(a) : "l"(p));
    return a;
}
__device__ __forceinline__ uint32_t sw128(uint32_t off) { return off ^ ((off >> 3) & 0x70); }

#define LDSM4(r, addr) \
    asm volatile("ldmatrix.sync.aligned.m8n8.x4.shared.b16 {%0,%1,%2,%3}, [%4];" \
        : "=r"((r)[0]), "=r"((r)[1]), "=r"((r)[2]), "=r"((r)[3]) : "r"(addr))

#define MMA16816(c, a, b0, b1) \
    asm volatile("mma.sync.aligned.m16n8k16.row.col.f32.bf16.bf16.f32 " \
        "{%0,%1,%2,%3}, {%4,%5,%6,%7}, {%8,%9}, {%0,%1,%2,%3};" \
        : "+f"((c)[0]), "+f"((c)[1]), "+f"((c)[2]), "+f"((c)[3]) \
        : "r"((a)[0]), "r"((a)[1]), "r"((a)[2]), "r"((a)[3]), "r"(b0), "r"(b1))

#define STS128(addr, v) \
    asm volatile("st.shared.v4.b32 [%0], {%1,%2,%3,%4};" \
        :: "r"(addr), "r"((v).x), "r"((v).y), "r"((v).z), "r"((v).w))

// ---------------------------------------------------------------------------
// fp32 -> bf16 hi/lo conversion.  sel: 0=x, 1=wq, 2=wk, 3=wv, 4=wo
// ---------------------------------------------------------------------------
__global__ __launch_bounds__(256) void convert_kernel(const float* __restrict__ src,
                                                      int sel, int n4)
{
    int i = blockIdx.x * 256 + threadIdx.x;
    if (i >= n4) return;
    __nv_bfloat16 *dh, *dl;
    switch (sel) {
        case 0: dh = g_xh;  dl = g_xl;  break;
        case 1: dh = g_wh0; dl = g_wl0; break;
        case 2: dh = g_wh1; dl = g_wl1; break;
        case 3: dh = g_wh2; dl = g_wl2; break;
        default: dh = g_wh3; dl = g_wl3; break;
    }
    float4 v = ((const float4*)src)[i];
    __nv_bfloat16 hx = __float2bfloat16(v.x);
    __nv_bfloat16 hy = __float2bfloat16(v.y);
    __nv_bfloat16 hz = __float2bfloat16(v.z);
    __nv_bfloat16 hw = __float2bfloat16(v.w);
    __nv_bfloat16 lx = __float2bfloat16(v.x - __bfloat162float(hx));
    __nv_bfloat16 ly = __float2bfloat16(v.y - __bfloat162float(hy));
    __nv_bfloat16 lz = __float2bfloat16(v.z - __bfloat162float(hz));
    __nv_bfloat16 lw = __float2bfloat16(v.w - __bfloat162float(hw));
    __nv_bfloat162 h01; h01.x = hx; h01.y = hy;
    __nv_bfloat162 h23; h23.x = hz; h23.y = hw;
    __nv_bfloat162 l01; l01.x = lx; l01.y = ly;
    __nv_bfloat162 l23; l23.x = lz; l23.y = lw;
    ((__nv_bfloat162*)dh)[i * 2]     = h01;
    ((__nv_bfloat162*)dh)[i * 2 + 1] = h23;
    ((__nv_bfloat162*)dl)[i * 2]     = l01;
    ((__nv_bfloat162*)dl)[i * 2 + 1] = l23;
}

// ---------------------------------------------------------------------------
// Tensor-core GEMM via mma.sync (bf16 hi/lo 3-pass, fp32 accumulate):
//   C[r][c] = sum_k A[r][k] * W[c][k]      M=4096, N=2048, K=2048
// 128x128 tile/CTA, BK=32, 256 thr (8 warps, 2x4, each 64x32).
// smem rows: 128B = [hi 64B | lo 64B], SW128 swizzle, double buffered.
// mode: 0 row-major Cout; 1 g_Q scatter; 2 g_K scatter; 3 g_V scatter.
// ---------------------------------------------------------------------------
__device__ __forceinline__ void epi_store2(int mode, float* __restrict__ Cout,
                                           int R, int C, float v0, float v1)
{
    float2 v = make_float2(v0, v1);
    if (mode == 0) {
        *(float2*)(Cout + (size_t)R * 2048 + C) = v;
    } else if (mode == 3) {
        int bb = R >> 11, s = R & 2047, hd = C >> 7, cc = C & 127;
        *(float2*)(g_V + ((size_t)(bb * 16 + hd) * 2048 + s) * 128 + cc) = v;
    } else {
        float* G = (mode == 1) ? g_Q : g_K;
        int bb = R >> 11, s = R & 2047, h2 = C >> 6, dd = C & 63;
        *(float2*)(G + ((size_t)(bb * 32 + h2) * 2048 + s) * 64 + dd) = v;
    }
}

__global__ __launch_bounds__(256) void gemm_mma(int asel, int wsel, int mode,
                                                float* __restrict__ Cout)
{
    extern __shared__ char dynsmem[];
    uint32_t sbase = (smem_u32(dynsmem) + 127) & ~127u;

    const int tid  = threadIdx.x;
    const int lane = tid & 31, wid = tid >> 5;
    const int wm = wid >> 2, wn = wid & 3;          // warp grid 2 x 4
    const int m0 = blockIdx.y * 128, n0 = blockIdx.x * 128;

    const __nv_bfloat16 *Ahp = asel ? g_Ah : g_xh;
    const __nv_bfloat16 *Alp = asel ? g_Al : g_xl;
    const __nv_bfloat16 *Bhp, *Blp;
    if      (wsel == 0) { Bhp = g_wh0; Blp = g_wl0; }
    else if (wsel == 1) { Bhp = g_wh1; Blp = g_wl1; }
    else if (wsel == 2) { Bhp = g_wh2; Blp = g_wl2; }
    else                { Bhp = g_wh3; Blp = g_wl3; }

    // per-thread load geometry (fixed across chunks):
    // i in 0..3: part = i>>1 (hi/lo), row = (i&1)*64 + tid/4, j = tid&3 (16B chunk)
    const int ldrow_lo = tid >> 2;
    const int ldj = tid & 3;
    uint32_t soff[4];
    #pragma unroll
    for (int i = 0; i < 4; i++) {
        int part = i >> 1, row = ((i & 1) << 6) + ldrow_lo;
        soff[i] = sw128((uint32_t)(row * 128 + part * 64 + ldj * 16));
    }

    float cacc[4][4][4];
    #pragma unroll
    for (int mt = 0; mt < 4; mt++)
        #pragma unroll
        for (int nt = 0; nt < 4; nt++)
            #pragma unroll
            for (int q = 0; q < 4; q++) cacc[mt][nt][q] = 0.f;

    uint4 areg[4], breg[4];

    // prologue: load chunk 0 into regs, store to stage 0
    #pragma unroll
    for (int i = 0; i < 4; i++) {
        int part = i >> 1, row = ((i & 1) << 6) + ldrow_lo;
        const __nv_bfloat16* As = part ? Alp : Ahp;
        const __nv_bfloat16* Bs = part ? Blp : Bhp;
        areg[i] = *(const uint4*)(As + (size_t)(m0 + row) * 2048 + ldj * 8);
        breg[i] = *(const uint4*)(Bs + (size_t)(n0 + row) * 2048 + ldj * 8);
    }
    #pragma unroll
    for (int i = 0; i < 4; i++) {
        STS128(sbase + soff[i], areg[i]);
        STS128(sbase + 16384 + soff[i], breg[i]);
    }
    __syncthreads();

    for (int chunk = 0; chunk < 64; chunk++) {
        int stg = chunk & 1;
        uint32_t aB = sbase + stg * 32768;
        uint32_t bB = aB + 16384;

        if (chunk < 63) {
            int kk = (chunk + 1) * 32;
            #pragma unroll
            for (int i = 0; i < 4; i++) {
                int part = i >> 1, row = ((i & 1) << 6) + ldrow_lo;
                const __nv_bfloat16* As = part ? Alp : Ahp;
                const __nv_bfloat16* Bs = part ? Blp : Bhp;
                areg[i] = *(const uint4*)(As + (size_t)(m0 + row) * 2048 + kk + ldj * 8);
                breg[i] = *(const uint4*)(Bs + (size_t)(n0 + row) * 2048 + kk + ldj * 8);
            }
        }

        #pragma unroll
        for (int ks = 0; ks < 2; ks++) {
            uint32_t colb = ks * 32 + ((lane >> 4) << 4);   // k-half select
            // B fragments: 2 ldmatrix.x4 per precision cover 4 n8-tiles
            uint32_t bfh[2][4], bfl[2][4];
            #pragma unroll
            for (int np = 0; np < 2; np++) {
                uint32_t brow = (uint32_t)(wn * 32 + np * 16 + (lane & 15));
                uint32_t off = brow * 128 + colb;
                LDSM4(bfh[np], bB + sw128(off));
                LDSM4(bfl[np], bB + sw128(off + 64));
            }
            #pragma unroll
            for (int mt = 0; mt < 4; mt++) {
                uint32_t arow = (uint32_t)(wm * 64 + mt * 16 + (lane & 15));
                uint32_t off = arow * 128 + colb;
                uint32_t ah[4], al[4];
                LDSM4(ah, aB + sw128(off));
                LDSM4(al, aB + sw128(off + 64));
                #pragma unroll
                for (int nt = 0; nt < 4; nt++) {
                    int np = nt >> 1, sel = nt & 1;
                    uint32_t b0h = bfh[np][sel], b1h = bfh[np][sel + 2];
                    uint32_t b0l = bfl[np][sel], b1l = bfl[np][sel + 2];
                    MMA16816(cacc[mt][nt], ah, b0h, b1h);   // Ah*Bh
                    MMA16816(cacc[mt][nt], ah, b0l, b1l);   // Ah*Bl
                    MMA16816(cacc[mt][nt], al, b0h, b1h);   // Al*Bh
                }
            }
        }

        if (chunk < 63) {
            uint32_t aN = sbase + (stg ^ 1) * 32768;
            #pragma unroll
            for (int i = 0; i < 4; i++) {
                STS128(aN + soff[i], areg[i]);
                STS128(aN + 16384 + soff[i], breg[i]);
            }
        }
        __syncthreads();
    }

    // epilogue: direct scatter from accumulators (float2 per store)
    #pragma unroll
    for (int mt = 0; mt < 4; mt++) {
        #pragma unroll
        for (int nt = 0; nt < 4; nt++) {
            int R = m0 + wm * 64 + mt * 16 + (lane >> 2);
            int C = n0 + wn * 32 + nt * 8 + ((lane & 3) << 1);
            epi_store2(mode, Cout, R,     C, cacc[mt][nt][0], cacc[mt][nt][1]);
            epi_store2(mode, Cout, R + 8, C, cacc[mt][nt][2], cacc[mt][nt][3]);
        }
    }
}

// ---------------------------------------------------------------------------
// RoPE in-place on g_Q/g_K
// ---------------------------------------------------------------------------
__global__ __launch_bounds__(256) void rope_kernel(const float* __restrict__ cosb,
                                                   const float* __restrict__ sinb)
{
    int idx = blockIdx.x * blockDim.x + threadIdx.x;
    const int total = 2 * 32 * 2048 * 32;
    if (idx >= total) return;
    int j = idx & 31;
    int s = (idx >> 5) & 2047;
    float c  = cosb[s * 32 + j];
    float sn = sinb[s * 32 + j];
    float2* q2 = (float2*)g_Q;
    float2* k2 = (float2*)g_K;
    float2 q = q2[idx];
    q2[idx] = make_float2(q.x * c - q.y * sn, q.x * sn + q.y * c);
    float2 k = k2[idx];
    k2[idx] = make_float2(k.x * c - k.y * sn, k.x * sn + k.y * c);
}

__global__ void lam_kernel(const float* __restrict__ lq1, const float* __restrict__ lk1,
                           const float* __restrict__ lq2, const float* __restrict__ lk2)
{
    if (threadIdx.x == 0) {
        float a = 0.f, b = 0.f;
        for (int i = 0; i < 64; i++) { a += lq1[i] * lk1[i]; b += lq2[i] * lk2[i]; }
        float li = 0.8f - 0.6f * expf(-9.6f);
        g_lam = expf(a) - expf(b) + li;
    }
}

// ---------------------------------------------------------------------------
// Causal flash attention (fp32) — unchanged from passing R4 kernel
// ---------------------------------------------------------------------------
__global__ __launch_bounds__(256) void attn_kernel()
{
    __shared__ __align__(16) float Qst[64 * 68];
    __shared__ __align__(16) float KstSs[64 * 36];
    __shared__ __align__(16) float Vs[32 * 128];
    __shared__ float mrow[64], lrow[64], arow[64];

    int tid = threadIdx.x;
    int unit = blockIdx.y;
    int b   = unit >> 5;
    int h   = (unit >> 1) & 15;
    int var = unit & 1;
    int q0  = blockIdx.x * 64;

    const float* Qg = g_Q + (size_t)(b * 32 + h * 2 + var) * 2048 * 64;
    const float* Kg = g_K + (size_t)(b * 32 + h * 2 + var) * 2048 * 64;
    const float* Vg = g_V + (size_t)(b * 16 + h) * 2048 * 128;
    float*       Og = g_O + (size_t)var * 8388608 + (size_t)(b * 16 + h) * 2048 * 128;

    #pragma unroll
    for (int t = 0; t < 16; t++) {
        int e = tid + t * 256;
        int i = e >> 6, d = e & 63;
        Qst[d * 68 + i] = Qg[(size_t)(q0 + i) * 64 + d];
    }
    if (tid < 64) { mrow[tid] = -1e30f; lrow[tid] = 0.f; }

    int ty = tid >> 4, tx = tid & 15;
    int rg = tid >> 4, cg = tid & 15;
    int srow = tid >> 2, part = tid & 3;

    float o[4][8];
    #pragma unroll
    for (int ii = 0; ii < 4; ii++)
        #pragma unroll
        for (int c = 0; c < 8; c++) o[ii][c] = 0.f;

    int nkt = (q0 >> 5) + 2;

    for (int kt = 0; kt < nkt; kt++) {
        __syncthreads();
        #pragma unroll
        for (int t = 0; t < 8; t++) {
            int e = tid + t * 256;
            int j = e >> 6, d = e & 63;
            KstSs[d * 36 + j] = Kg[(size_t)(kt * 32 + j) * 64 + d];
        }
        #pragma unroll
        for (int t = 0; t < 4; t++) {
            int e = tid + t * 256;
            int j = e >> 5, c4 = e & 31;
            *(float4*)&Vs[j * 128 + c4 * 4] =
                *(const float4*)&Vg[(size_t)(kt * 32 + j) * 128 + c4 * 4];
        }
        __syncthreads();

        float acc[4][2] = {};
        #pragma unroll 16
        for (int d = 0; d < 64; d++) {
            float4 a  = *(const float4*)&Qst[d * 68 + ty * 4];
            float2 bv = *(const float2*)&KstSs[d * 36 + tx * 2];
            acc[0][0] += a.x * bv.x; acc[0][1] += a.x * bv.y;
            acc[1][0] += a.y * bv.x; acc[1][1] += a.y * bv.y;
            acc[2][0] += a.z * bv.x; acc[2][1] += a.z * bv.y;
            acc[3][0] += a.w * bv.x; acc[3][1] += a.w * bv.y;
        }
        __syncthreads();

        bool needmask = (kt * 32 + 31) > q0;
        #pragma unroll
        for (int ii = 0; ii < 4; ii++) {
            int row = ty * 4 + ii;
            #pragma unroll
            for (int jj = 0; jj < 2; jj++) {
                int col = tx * 2 + jj;
                float sv = acc[ii][jj] * 0.125f;
                if (needmask && (kt * 32 + col > q0 + row)) sv = -1e30f;
                KstSs[row * 33 + col] = sv;
            }
        }
        __syncthreads();

        {
            float sv[8]; float mx = -1e30f;
            #pragma unroll
            for (int k2 = 0; k2 < 8; k2++) {
                sv[k2] = KstSs[srow * 33 + part * 8 + k2];
                mx = fmaxf(mx, sv[k2]);
            }
            mx = fmaxf(mx, __shfl_xor_sync(0xffffffffu, mx, 1));
            mx = fmaxf(mx, __shfl_xor_sync(0xffffffffu, mx, 2));
            float mold = mrow[srow];
            float mnew = fmaxf(mold, mx);
            float psum = 0.f;
            #pragma unroll
            for (int k2 = 0; k2 < 8; k2++) {
                float p = __expf(sv[k2] - mnew);
                KstSs[srow * 33 + part * 8 + k2] = p;
                psum += p;
            }
            psum += __shfl_xor_sync(0xffffffffu, psum, 1);
            psum += __shfl_xor_sync(0xffffffffu, psum, 2);
            if (part == 0) {
                float al = __expf(mold - mnew);
                arow[srow] = al;
                lrow[srow] = lrow[srow] * al + psum;
                mrow[srow] = mnew;
            }
        }
        __syncthreads();

        {
            float al[4];
            #pragma unroll
            for (int ii = 0; ii < 4; ii++) al[ii] = arow[rg * 4 + ii];
            #pragma unroll
            for (int ii = 0; ii < 4; ii++)
                #pragma unroll
                for (int c = 0; c < 8; c++) o[ii][c] *= al[ii];

            #pragma unroll 4
            for (int j = 0; j < 32; j++) {
                float4 v0 = *(const float4*)&Vs[j * 128 + cg * 8];
                float4 v1 = *(const float4*)&Vs[j * 128 + cg * 8 + 4];
                float vv[8] = {v0.x, v0.y, v0.z, v0.w, v1.x, v1.y, v1.z, v1.w};
                float pp[4];
                #pragma unroll
                for (int ii = 0; ii < 4; ii++) pp[ii] = KstSs[(rg * 4 + ii) * 33 + j];
                #pragma unroll
                for (int ii = 0; ii < 4; ii++)
                    #pragma unroll
                    for (int c = 0; c < 8; c++)
                        o[ii][c] += pp[ii] * vv[c];
            }
        }
    }

    #pragma unroll
    for (int ii = 0; ii < 4; ii++) {
        float linv = 1.0f / lrow[rg * 4 + ii];
        float4 r0 = make_float4(o[ii][0] * linv, o[ii][1] * linv,
                                o[ii][2] * linv, o[ii][3] * linv);
        float4 r1 = make_float4(o[ii][4] * linv, o[ii][5] * linv,
                                o[ii][6] * linv, o[ii][7] * linv);
        size_t base = (size_t)(q0 + rg * 4 + ii) * 128 + cg * 8;
        *(float4*)&Og[base]     = r0;
        *(float4*)&Og[base + 4] = r1;
    }
}

// ---------------------------------------------------------------------------
// Combine: attn = (O1 - lam*O2); RMSNorm(128); * subln_w * (1-LAMBDA_INIT)
// Emits bf16 hi/lo directly into g_Ah/g_Al (GEMM-ready row-major).
// ---------------------------------------------------------------------------
__global__ __launch_bounds__(256) void combine_kernel(const float* __restrict__ subw)
{
    int warp = threadIdx.x >> 5, lane = threadIdx.x & 31;
    int v = blockIdx.x * 8 + warp;        // (b*16+h)*2048 + s
    const float4* p1 = (const float4*)g_O + (size_t)v * 32;
    const float4* p2 = (const float4*)(g_O + 8388608) + (size_t)v * 32;

    float lam = g_lam;
    float4 x1 = p1[lane], x2 = p2[lane];
    float4 a = make_float4(x1.x - lam * x2.x, x1.y - lam * x2.y,
                           x1.z - lam * x2.z, x1.w - lam * x2.w);
    float ss = a.x * a.x + a.y * a.y + a.z * a.z + a.w * a.w;
    #pragma unroll
    for (int off = 16; off > 0; off >>= 1)
        ss += __shfl_xor_sync(0xffffffffu, ss, off);

    float li = 0.8f - 0.6f * expf(-9.6f);
    float sc = rsqrtf(ss * (1.0f / 128.0f) + 1e-5f) * (1.0f - li);
    float4 w = ((const float4*)subw)[lane];
    float4 out = make_float4(a.x * sc * w.x, a.y * sc * w.y,
                             a.z * sc * w.z, a.w * sc * w.w);

    int bb = v >> 15;
    int hh = (v >> 11) & 15;
    int s  = v & 2047;
    size_t base = (size_t)(bb * 2048 + s) * 2048 + hh * 128 + lane * 4;

    __nv_bfloat16 h0 = __float2bfloat16(out.x);
    __nv_bfloat16 h1 = __float2bfloat16(out.y);
    __nv_bfloat16 h2 = __float2bfloat16(out.z);
    __nv_bfloat16 h3 = __float2bfloat16(out.w);
    __nv_bfloat16 l0 = __float2bfloat16(out.x - __bfloat162float(h0));
    __nv_bfloat16 l1 = __float2bfloat16(out.y - __bfloat162float(h1));
    __nv_bfloat16 l2 = __float2bfloat16(out.z - __bfloat162float(h2));
    __nv_bfloat16 l3 = __float2bfloat16(out.w - __bfloat162float(h3));
    __nv_bfloat162 ha; ha.x = h0; ha.y = h1;
    __nv_bfloat162 hb; hb.x = h2; hb.y = h3;
    __nv_bfloat162 la; la.x = l0; la.y = l1;
    __nv_bfloat162 lb; lb.x = l2; lb.y = l3;
    ((__nv_bfloat162*)(g_Ah + base))[0] = ha;
    ((__nv_bfloat162*)(g_Ah + base))[1] = hb;
    ((__nv_bfloat162*)(g_Al + base))[0] = la;
    ((__nv_bfloat162*)(g_Al + base))[1] = lb;
}

// ---------------------------------------------------------------------------
extern "C" void kernel_launch(void* const* d_in, const int* in_sizes, int n_in,
                              void* d_out, int out_size)
{
    const float* x    = (const float*)d_in[0];
    const float* wq   = (const float*)d_in[1];
    const float* wk   = (const float*)d_in[2];
    const float* wv   = (const float*)d_in[3];
    const float* wo   = (const float*)d_in[4];
    const float* lq1  = (const float*)d_in[5];
    const float* lk1  = (const float*)d_in[6];
    const float* lq2  = (const float*)d_in[7];
    const float* lk2  = (const float*)d_in[8];
    const float* subw = (const float*)d_in[9];
    const float* rc   = (const float*)d_in[10];
    const float* rs   = (const float*)d_in[11];

    const int SMEM_BYTES = 65536 + 128;
    static int attr_set = 0;
    if (!attr_set) {
        cudaFuncSetAttribute(gemm_mma, cudaFuncAttributeMaxDynamicSharedMemorySize, SMEM_BYTES);
        attr_set = 1;
    }

    dim3 gemm_grid(16, 32), gemm_blk(256);

    convert_kernel<<<8192, 256>>>(x,  0, 2097152);
    convert_kernel<<<4096, 256>>>(wq, 1, 1048576);
    convert_kernel<<<4096, 256>>>(wk, 2, 1048576);
    convert_kernel<<<4096, 256>>>(wv, 3, 1048576);
    convert_kernel<<<4096, 256>>>(wo, 4, 1048576);

    gemm_mma<<<gemm_grid, gemm_blk, SMEM_BYTES>>>(0, 0, 1, nullptr);  // Q
    gemm_mma<<<gemm_grid, gemm_blk, SMEM_BYTES>>>(0, 1, 2, nullptr);  // K
    gemm_mma<<<gemm_grid, gemm_blk, SMEM_BYTES>>>(0, 2, 3, nullptr);  // V

    rope_kernel<<<16384, 256>>>(rc, rs);
    lam_kernel<<<1, 32>>>(lq1, lk1, lq2, lk2);
    attn_kernel<<<dim3(32, 64), 256>>>();
    combine_kernel<<<8192, 256>>>(subw);

    gemm_mma<<<gemm_grid, gemm_blk, SMEM_BYTES>>>(1, 3, 0, (float*)d_out);  // out proj
}

// round 12
// speedup vs baseline: 1.6414x; 1.0458x over previous
#include <cuda_runtime.h>
#include <cuda_bf16.h>
#include <math.h>
#include <stdint.h>

// Shapes: BSZ=2, SEQ=2048, DIM=2048, N_HEADS=16, HEAD_DIM=64 (2 variants/head)
// fp32 scratch
__device__ float g_Q[8388608];   // [b][head2(32)][s][64]
__device__ float g_K[8388608];   // [b][head2(32)][s][64]
__device__ float g_V[8388608];   // [b][h(16)][s][128]
__device__ float g_O[16777216];  // [var(2)][b][h][s][128]
__device__ float g_lam;

// bf16 hi/lo operand scratch for tensor-core GEMMs
__device__ __nv_bfloat16 g_xh[8388608], g_xl[8388608];   // x  [4096][2048]
__device__ __nv_bfloat16 g_Ah[8388608], g_Al[8388608];   // combine out [4096][2048]
__device__ __nv_bfloat16 g_wh0[4194304], g_wl0[4194304]; // wq
__device__ __nv_bfloat16 g_wh1[4194304], g_wl1[4194304]; // wk
__device__ __nv_bfloat16 g_wh2[4194304], g_wl2[4194304]; // wv
__device__ __nv_bfloat16 g_wh3[4194304], g_wl3[4194304]; // wo

// ---------------------------------------------------------------------------
// Helpers (all base-ISA: ldmatrix sm_75+, bf16 mma.sync + cp.async sm_80+)
// ---------------------------------------------------------------------------
__device__ __forceinline__ uint32_t smem_u32(const void* p) {
    uint32_t a;
    asm("{ .reg .u64 t; cvta.to.shared.u64 t, %1; cvt.u32.u64 %0, t; }" : "=r"(a) : "l"(p));
    return a;
}
__device__ __forceinline__ uint32_t sw128(uint32_t off) { return off ^ ((off >> 3) & 0x70); }

#define LDSM4(r, addr) \
    asm volatile("ldmatrix.sync.aligned.m8n8.x4.shared.b16 {%0,%1,%2,%3}, [%4];" \
        : "=r"((r)[0]), "=r"((r)[1]), "=r"((r)[2]), "=r"((r)[3]) : "r"(addr))

#define MMA16816(c, a, b0, b1) \
    asm volatile("mma.sync.aligned.m16n8k16.row.col.f32.bf16.bf16.f32 " \
        "{%0,%1,%2,%3}, {%4,%5,%6,%7}, {%8,%9}, {%0,%1,%2,%3};" \
        : "+f"((c)[0]), "+f"((c)[1]), "+f"((c)[2]), "+f"((c)[3]) \
        : "r"((a)[0]), "r"((a)[1]), "r"((a)[2]), "r"((a)[3]), "r"(b0), "r"(b1))

#define CP16(dst, src) \
    asm volatile("cp.async.cg.shared.global [%0], [%1], 16;" :: "r"(dst), "l"(src))
#define CP_COMMIT() asm volatile("cp.async.commit_group;")
#define CP_WAIT1()  asm volatile("cp.async.wait_group 1;" ::: "memory")
#define CP_WAIT0()  asm volatile("cp.async.wait_group 0;" ::: "memory")

// ---------------------------------------------------------------------------
// fp32 -> bf16 hi/lo conversion.  sel: 0=x, 1=wq, 2=wk, 3=wv, 4=wo
// ---------------------------------------------------------------------------
__global__ __launch_bounds__(256) void convert_kernel(const float* __restrict__ src,
                                                      int sel, int n4)
{
    int i = blockIdx.x * 256 + threadIdx.x;
    if (i >= n4) return;
    __nv_bfloat16 *dh, *dl;
    switch (sel) {
        case 0: dh = g_xh;  dl = g_xl;  break;
        case 1: dh = g_wh0; dl = g_wl0; break;
        case 2: dh = g_wh1; dl = g_wl1; break;
        case 3: dh = g_wh2; dl = g_wl2; break;
        default: dh = g_wh3; dl = g_wl3; break;
    }
    float4 v = ((const float4*)src)[i];
    __nv_bfloat16 hx = __float2bfloat16(v.x);
    __nv_bfloat16 hy = __float2bfloat16(v.y);
    __nv_bfloat16 hz = __float2bfloat16(v.z);
    __nv_bfloat16 hw = __float2bfloat16(v.w);
    __nv_bfloat16 lx = __float2bfloat16(v.x - __bfloat162float(hx));
    __nv_bfloat16 ly = __float2bfloat16(v.y - __bfloat162float(hy));
    __nv_bfloat16 lz = __float2bfloat16(v.z - __bfloat162float(hz));
    __nv_bfloat16 lw = __float2bfloat16(v.w - __bfloat162float(hw));
    __nv_bfloat162 h01; h01.x = hx; h01.y = hy;
    __nv_bfloat162 h23; h23.x = hz; h23.y = hw;
    __nv_bfloat162 l01; l01.x = lx; l01.y = ly;
    __nv_bfloat162 l23; l23.x = lz; l23.y = lw;
    ((__nv_bfloat162*)dh)[i * 2]     = h01;
    ((__nv_bfloat162*)dh)[i * 2 + 1] = h23;
    ((__nv_bfloat162*)dl)[i * 2]     = l01;
    ((__nv_bfloat162*)dl)[i * 2 + 1] = l23;
}

// ---------------------------------------------------------------------------
// Tensor-core GEMM via mma.sync (bf16 hi/lo 3-pass, fp32 accumulate):
//   C[r][c] = sum_k A[r][k] * W[c][k]      M=4096, N=2048, K=2048
// 128x128 tile/CTA, BK=32, 256 thr (8 warps 2x4, each 64x32 out).
// cp.async 3-stage pipeline; smem rows 128B = [hi 64B | lo 64B], SW128.
// mode: 0 row-major Cout; 1 g_Q scatter; 2 g_K scatter; 3 g_V scatter.
// ---------------------------------------------------------------------------
__device__ __forceinline__ void epi_store2(int mode, float* __restrict__ Cout,
                                           int R, int C, float v0, float v1)
{
    float2 v = make_float2(v0, v1);
    if (mode == 0) {
        *(float2*)(Cout + (size_t)R * 2048 + C) = v;
    } else if (mode == 3) {
        int bb = R >> 11, s = R & 2047, hd = C >> 7, cc = C & 127;
        *(float2*)(g_V + ((size_t)(bb * 16 + hd) * 2048 + s) * 128 + cc) = v;
    } else {
        float* G = (mode == 1) ? g_Q : g_K;
        int bb = R >> 11, s = R & 2047, h2 = C >> 6, dd = C & 63;
        *(float2*)(G + ((size_t)(bb * 32 + h2) * 2048 + s) * 64 + dd) = v;
    }
}

__global__ __launch_bounds__(256, 2) void gemm_mma(int asel, int wsel, int mode,
                                                   float* __restrict__ Cout)
{
    extern __shared__ char dynsmem[];
    uint32_t sbase = (smem_u32(dynsmem) + 127) & ~127u;

    const int tid  = threadIdx.x;
    const int lane = tid & 31, wid = tid >> 5;
    const int wm = wid >> 2, wn = wid & 3;          // warp grid 2 x 4
    const int m0 = blockIdx.y * 128, n0 = blockIdx.x * 128;

    const __nv_bfloat16 *Ahp = asel ? g_Ah : g_xh;
    const __nv_bfloat16 *Alp = asel ? g_Al : g_xl;
    const __nv_bfloat16 *Bhp, *Blp;
    if      (wsel == 0) { Bhp = g_wh0; Blp = g_wl0; }
    else if (wsel == 1) { Bhp = g_wh1; Blp = g_wl1; }
    else if (wsel == 2) { Bhp = g_wh2; Blp = g_wl2; }
    else                { Bhp = g_wh3; Blp = g_wl3; }

    // per-thread copy geometry (fixed): i in 0..3 -> part = i>>1 (hi/lo),
    // row = (i&1)*64 + tid/4, 16B chunk j = tid&3
    const int ldrow_lo = tid >> 2;
    const int ldj = tid & 3;
    const __nv_bfloat16* asrc[4];
    const __nv_bfloat16* bsrc[4];
    uint32_t soff[4];
    #pragma unroll
    for (int i = 0; i < 4; i++) {
        int part = i >> 1, row = ((i & 1) << 6) + ldrow_lo;
        const __nv_bfloat16* As = part ? Alp : Ahp;
        const __nv_bfloat16* Bs = part ? Blp : Bhp;
        asrc[i] = As + (size_t)(m0 + row) * 2048 + ldj * 8;
        bsrc[i] = Bs + (size_t)(n0 + row) * 2048 + ldj * 8;
        soff[i] = sw128((uint32_t)(row * 128 + part * 64 + ldj * 16));
    }

    float cacc[4][4][4];
    #pragma unroll
    for (int mt = 0; mt < 4; mt++)
        #pragma unroll
        for (int nt = 0; nt < 4; nt++)
            #pragma unroll
            for (int q = 0; q < 4; q++) cacc[mt][nt][q] = 0.f;

    // prologue: stages 0,1 <- chunks 0,1
    #pragma unroll
    for (int c = 0; c < 2; c++) {
        uint32_t st = sbase + c * 32768;
        #pragma unroll
        for (int i = 0; i < 4; i++) {
            CP16(st + soff[i],         asrc[i] + c * 32);
            CP16(st + 16384 + soff[i], bsrc[i] + c * 32);
        }
        CP_COMMIT();
    }

    for (int chunk = 0; chunk < 64; chunk++) {
        // data for `chunk` ready when pending groups <= 1 (or 0 at the tail)
        if (chunk == 63) { CP_WAIT0(); } else { CP_WAIT1(); }
        __syncthreads();

        // issue chunk+2 into stage (chunk+2)%3 == (chunk-1)%3 (freed by the barrier)
        if (chunk + 2 < 64) {
            int nc = chunk + 2;
            uint32_t st = sbase + (nc % 3) * 32768;
            #pragma unroll
            for (int i = 0; i < 4; i++) {
                CP16(st + soff[i],         asrc[i] + nc * 32);
                CP16(st + 16384 + soff[i], bsrc[i] + nc * 32);
            }
            CP_COMMIT();
        }

        uint32_t aB = sbase + (chunk % 3) * 32768;
        uint32_t bB = aB + 16384;

        #pragma unroll
        for (int ks = 0; ks < 2; ks++) {
            uint32_t colb = ks * 32 + ((lane >> 4) << 4);   // k-half select
            uint32_t bfh[2][4], bfl[2][4];
            #pragma unroll
            for (int np = 0; np < 2; np++) {
                uint32_t brow = (uint32_t)(wn * 32 + np * 16 + (lane & 15));
                uint32_t off = brow * 128 + colb;
                LDSM4(bfh[np], bB + sw128(off));
                LDSM4(bfl[np], bB + sw128(off + 64));
            }
            #pragma unroll
            for (int mt = 0; mt < 4; mt++) {
                uint32_t arow = (uint32_t)(wm * 64 + mt * 16 + (lane & 15));
                uint32_t off = arow * 128 + colb;
                uint32_t ah[4], al[4];
                LDSM4(ah, aB + sw128(off));
                LDSM4(al, aB + sw128(off + 64));
                #pragma unroll
                for (int nt = 0; nt < 4; nt++) {
                    int np = nt >> 1, sel = nt & 1;
                    uint32_t b0h = bfh[np][sel], b1h = bfh[np][sel + 2];
                    uint32_t b0l = bfl[np][sel], b1l = bfl[np][sel + 2];
                    MMA16816(cacc[mt][nt], ah, b0h, b1h);   // Ah*Bh
                    MMA16816(cacc[mt][nt], ah, b0l, b1l);   // Ah*Bl
                    MMA16816(cacc[mt][nt], al, b0h, b1h);   // Al*Bh
                }
            }
        }
        __syncthreads();
    }

    // epilogue: direct scatter from accumulators (float2 per store)
    #pragma unroll
    for (int mt = 0; mt < 4; mt++) {
        #pragma unroll
        for (int nt = 0; nt < 4; nt++) {
            int R = m0 + wm * 64 + mt * 16 + (lane >> 2);
            int C = n0 + wn * 32 + nt * 8 + ((lane & 3) << 1);
            epi_store2(mode, Cout, R,     C, cacc[mt][nt][0], cacc[mt][nt][1]);
            epi_store2(mode, Cout, R + 8, C, cacc[mt][nt][2], cacc[mt][nt][3]);
        }
    }
}

// ---------------------------------------------------------------------------
// RoPE in-place on g_Q/g_K
// ---------------------------------------------------------------------------
__global__ __launch_bounds__(256) void rope_kernel(const float* __restrict__ cosb,
                                                   const float* __restrict__ sinb)
{
    int idx = blockIdx.x * blockDim.x + threadIdx.x;
    const int total = 2 * 32 * 2048 * 32;
    if (idx >= total) return;
    int j = idx & 31;
    int s = (idx >> 5) & 2047;
    float c  = cosb[s * 32 + j];
    float sn = sinb[s * 32 + j];
    float2* q2 = (float2*)g_Q;
    float2* k2 = (float2*)g_K;
    float2 q = q2[idx];
    q2[idx] = make_float2(q.x * c - q.y * sn, q.x * sn + q.y * c);
    float2 k = k2[idx];
    k2[idx] = make_float2(k.x * c - k.y * sn, k.x * sn + k.y * c);
}

__global__ void lam_kernel(const float* __restrict__ lq1, const float* __restrict__ lk1,
                           const float* __restrict__ lq2, const float* __restrict__ lk2)
{
    if (threadIdx.x == 0) {
        float a = 0.f, b = 0.f;
        for (int i = 0; i < 64; i++) { a += lq1[i] * lk1[i]; b += lq2[i] * lk2[i]; }
        float li = 0.8f - 0.6f * expf(-9.6f);
        g_lam = expf(a) - expf(b) + li;
    }
}

// ---------------------------------------------------------------------------
// Causal flash attention (fp32) — unchanged from passing R11 kernel
// ---------------------------------------------------------------------------
__global__ __launch_bounds__(256) void attn_kernel()
{
    __shared__ __align__(16) float Qst[64 * 68];
    __shared__ __align__(16) float KstSs[64 * 36];
    __shared__ __align__(16) float Vs[32 * 128];
    __shared__ float mrow[64], lrow[64], arow[64];

    int tid = threadIdx.x;
    int unit = blockIdx.y;
    int b   = unit >> 5;
    int h   = (unit >> 1) & 15;
    int var = unit & 1;
    int q0  = blockIdx.x * 64;

    const float* Qg = g_Q + (size_t)(b * 32 + h * 2 + var) * 2048 * 64;
    const float* Kg = g_K + (size_t)(b * 32 + h * 2 + var) * 2048 * 64;
    const float* Vg = g_V + (size_t)(b * 16 + h) * 2048 * 128;
    float*       Og = g_O + (size_t)var * 8388608 + (size_t)(b * 16 + h) * 2048 * 128;

    #pragma unroll
    for (int t = 0; t < 16; t++) {
        int e = tid + t * 256;
        int i = e >> 6, d = e & 63;
        Qst[d * 68 + i] = Qg[(size_t)(q0 + i) * 64 + d];
    }
    if (tid < 64) { mrow[tid] = -1e30f; lrow[tid] = 0.f; }

    int ty = tid >> 4, tx = tid & 15;
    int rg = tid >> 4, cg = tid & 15;
    int srow = tid >> 2, part = tid & 3;

    float o[4][8];
    #pragma unroll
    for (int ii = 0; ii < 4; ii++)
        #pragma unroll
        for (int c = 0; c < 8; c++) o[ii][c] = 0.f;

    int nkt = (q0 >> 5) + 2;

    for (int kt = 0; kt < nkt; kt++) {
        __syncthreads();
        #pragma unroll
        for (int t = 0; t < 8; t++) {
            int e = tid + t * 256;
            int j = e >> 6, d = e & 63;
            KstSs[d * 36 + j] = Kg[(size_t)(kt * 32 + j) * 64 + d];
        }
        #pragma unroll
        for (int t = 0; t < 4; t++) {
            int e = tid + t * 256;
            int j = e >> 5, c4 = e & 31;
            *(float4*)&Vs[j * 128 + c4 * 4] =
                *(const float4*)&Vg[(size_t)(kt * 32 + j) * 128 + c4 * 4];
        }
        __syncthreads();

        float acc[4][2] = {};
        #pragma unroll 16
        for (int d = 0; d < 64; d++) {
            float4 a  = *(const float4*)&Qst[d * 68 + ty * 4];
            float2 bv = *(const float2*)&KstSs[d * 36 + tx * 2];
            acc[0][0] += a.x * bv.x; acc[0][1] += a.x * bv.y;
            acc[1][0] += a.y * bv.x; acc[1][1] += a.y * bv.y;
            acc[2][0] += a.z * bv.x; acc[2][1] += a.z * bv.y;
            acc[3][0] += a.w * bv.x; acc[3][1] += a.w * bv.y;
        }
        __syncthreads();

        bool needmask = (kt * 32 + 31) > q0;
        #pragma unroll
        for (int ii = 0; ii < 4; ii++) {
            int row = ty * 4 + ii;
            #pragma unroll
            for (int jj = 0; jj < 2; jj++) {
                int col = tx * 2 + jj;
                float sv = acc[ii][jj] * 0.125f;
                if (needmask && (kt * 32 + col > q0 + row)) sv = -1e30f;
                KstSs[row * 33 + col] = sv;
            }
        }
        __syncthreads();

        {
            float sv[8]; float mx = -1e30f;
            #pragma unroll
            for (int k2 = 0; k2 < 8; k2++) {
                sv[k2] = KstSs[srow * 33 + part * 8 + k2];
                mx = fmaxf(mx, sv[k2]);
            }
            mx = fmaxf(mx, __shfl_xor_sync(0xffffffffu, mx, 1));
            mx = fmaxf(mx, __shfl_xor_sync(0xffffffffu, mx, 2));
            float mold = mrow[srow];
            float mnew = fmaxf(mold, mx);
            float psum = 0.f;
            #pragma unroll
            for (int k2 = 0; k2 < 8; k2++) {
                float p = __expf(sv[k2] - mnew);
                KstSs[srow * 33 + part * 8 + k2] = p;
                psum += p;
            }
            psum += __shfl_xor_sync(0xffffffffu, psum, 1);
            psum += __shfl_xor_sync(0xffffffffu, psum, 2);
            if (part == 0) {
                float al = __expf(mold - mnew);
                arow[srow] = al;
                lrow[srow] = lrow[srow] * al + psum;
                mrow[srow] = mnew;
            }
        }
        __syncthreads();

        {
            float al[4];
            #pragma unroll
            for (int ii = 0; ii < 4; ii++) al[ii] = arow[rg * 4 + ii];
            #pragma unroll
            for (int ii = 0; ii < 4; ii++)
                #pragma unroll
                for (int c = 0; c < 8; c++) o[ii][c] *= al[ii];

            #pragma unroll 4
            for (int j = 0; j < 32; j++) {
                float4 v0 = *(const float4*)&Vs[j * 128 + cg * 8];
                float4 v1 = *(const float4*)&Vs[j * 128 + cg * 8 + 4];
                float vv[8] = {v0.x, v0.y, v0.z, v0.w, v1.x, v1.y, v1.z, v1.w};
                float pp[4];
                #pragma unroll
                for (int ii = 0; ii < 4; ii++) pp[ii] = KstSs[(rg * 4 + ii) * 33 + j];
                #pragma unroll
                for (int ii = 0; ii < 4; ii++)
                    #pragma unroll
                    for (int c = 0; c < 8; c++)
                        o[ii][c] += pp[ii] * vv[c];
            }
        }
    }

    #pragma unroll
    for (int ii = 0; ii < 4; ii++) {
        float linv = 1.0f / lrow[rg * 4 + ii];
        float4 r0 = make_float4(o[ii][0] * linv, o[ii][1] * linv,
                                o[ii][2] * linv, o[ii][3] * linv);
        float4 r1 = make_float4(o[ii][4] * linv, o[ii][5] * linv,
                                o[ii][6] * linv, o[ii][7] * linv);
        size_t base = (size_t)(q0 + rg * 4 + ii) * 128 + cg * 8;
        *(float4*)&Og[base]     = r0;
        *(float4*)&Og[base + 4] = r1;
    }
}

// ---------------------------------------------------------------------------
// Combine: attn = (O1 - lam*O2); RMSNorm(128); * subln_w * (1-LAMBDA_INIT)
// Emits bf16 hi/lo directly into g_Ah/g_Al (GEMM-ready row-major).
// ---------------------------------------------------------------------------
__global__ __launch_bounds__(256) void combine_kernel(const float* __restrict__ subw)
{
    int warp = threadIdx.x >> 5, lane = threadIdx.x & 31;
    int v = blockIdx.x * 8 + warp;        // (b*16+h)*2048 + s
    const float4* p1 = (const float4*)g_O + (size_t)v * 32;
    const float4* p2 = (const float4*)(g_O + 8388608) + (size_t)v * 32;

    float lam = g_lam;
    float4 x1 = p1[lane], x2 = p2[lane];
    float4 a = make_float4(x1.x - lam * x2.x, x1.y - lam * x2.y,
                           x1.z - lam * x2.z, x1.w - lam * x2.w);
    float ss = a.x * a.x + a.y * a.y + a.z * a.z + a.w * a.w;
    #pragma unroll
    for (int off = 16; off > 0; off >>= 1)
        ss += __shfl_xor_sync(0xffffffffu, ss, off);

    float li = 0.8f - 0.6f * expf(-9.6f);
    float sc = rsqrtf(ss * (1.0f / 128.0f) + 1e-5f) * (1.0f - li);
    float4 w = ((const float4*)subw)[lane];
    float4 out = make_float4(a.x * sc * w.x, a.y * sc * w.y,
                             a.z * sc * w.z, a.w * sc * w.w);

    int bb = v >> 15;
    int hh = (v >> 11) & 15;
    int s  = v & 2047;
    size_t base = (size_t)(bb * 2048 + s) * 2048 + hh * 128 + lane * 4;

    __nv_bfloat16 h0 = __float2bfloat16(out.x);
    __nv_bfloat16 h1 = __float2bfloat16(out.y);
    __nv_bfloat16 h2 = __float2bfloat16(out.z);
    __nv_bfloat16 h3 = __float2bfloat16(out.w);
    __nv_bfloat16 l0 = __float2bfloat16(out.x - __bfloat162float(h0));
    __nv_bfloat16 l1 = __float2bfloat16(out.y - __bfloat162float(h1));
    __nv_bfloat16 l2 = __float2bfloat16(out.z - __bfloat162float(h2));
    __nv_bfloat16 l3 = __float2bfloat16(out.w - __bfloat162float(h3));
    __nv_bfloat162 ha; ha.x = h0; ha.y = h1;
    __nv_bfloat162 hb; hb.x = h2; hb.y = h3;
    __nv_bfloat162 la; la.x = l0; la.y = l1;
    __nv_bfloat162 lb; lb.x = l2; lb.y = l3;
    ((__nv_bfloat162*)(g_Ah + base))[0] = ha;
    ((__nv_bfloat162*)(g_Ah + base))[1] = hb;
    ((__nv_bfloat162*)(g_Al + base))[0] = la;
    ((__nv_bfloat162*)(g_Al + base))[1] = lb;
}

// ---------------------------------------------------------------------------
extern "C" void kernel_launch(void* const* d_in, const int* in_sizes, int n_in,
                              void* d_out, int out_size)
{
    const float* x    = (const float*)d_in[0];
    const float* wq   = (const float*)d_in[1];
    const float* wk   = (const float*)d_in[2];
    const float* wv   = (const float*)d_in[3];
    const float* wo   = (const float*)d_in[4];
    const float* lq1  = (const float*)d_in[5];
    const float* lk1  = (const float*)d_in[6];
    const float* lq2  = (const float*)d_in[7];
    const float* lk2  = (const float*)d_in[8];
    const float* subw = (const float*)d_in[9];
    const float* rc   = (const float*)d_in[10];
    const float* rs   = (const float*)d_in[11];

    const int SMEM_BYTES = 3 * 32768 + 128;   // 3-stage pipeline
    static int attr_set = 0;
    if (!attr_set) {
        cudaFuncSetAttribute(gemm_mma, cudaFuncAttributeMaxDynamicSharedMemorySize, SMEM_BYTES);
        attr_set = 1;
    }

    dim3 gemm_grid(16, 32), gemm_blk(256);

    convert_kernel<<<8192, 256>>>(x,  0, 2097152);
    convert_kernel<<<4096, 256>>>(wq, 1, 1048576);
    convert_kernel<<<4096, 256>>>(wk, 2, 1048576);
    convert_kernel<<<4096, 256>>>(wv, 3, 1048576);
    convert_kernel<<<4096, 256>>>(wo, 4, 1048576);

    gemm_mma<<<gemm_grid, gemm_blk, SMEM_BYTES>>>(0, 0, 1, nullptr);  // Q
    gemm_mma<<<gemm_grid, gemm_blk, SMEM_BYTES>>>(0, 1, 2, nullptr);  // K
    gemm_mma<<<gemm_grid, gemm_blk, SMEM_BYTES>>>(0, 2, 3, nullptr);  // V

    rope_kernel<<<16384, 256>>>(rc, rs);
    lam_kernel<<<1, 32>>>(lq1, lk1, lq2, lk2);
    attn_kernel<<<dim3(32, 64), 256>>>();
    combine_kernel<<<8192, 256>>>(subw);

    gemm_mma<<<gemm_grid, gemm_blk, SMEM_BYTES>>>(1, 3, 0, (float*)d_out);  // out proj
}

// round 15
// speedup vs baseline: 1.7038x; 1.0380x over previous
#include <cuda_runtime.h>
#include <cuda_bf16.h>
#include <math.h>
#include <stdint.h>

// Shapes: BSZ=2, SEQ=2048, DIM=2048, N_HEADS=16, HEAD_DIM=64 (2 variants/head)
// fp32 scratch
__device__ float g_Q[8388608];   // [b][head2(32)][s][64]
__device__ float g_K[8388608];   // [b][head2(32)][s][64]
__device__ float g_V[8388608];   // [b][h(16)][s][128]
__device__ float g_O[16777216];  // [var(2)][b][h][s][128]
__device__ float g_lam;

// bf16 hi/lo operand scratch for tensor-core GEMMs
__device__ __nv_bfloat16 g_xh[8388608], g_xl[8388608];   // x  [4096][2048]
__device__ __nv_bfloat16 g_Ah[8388608], g_Al[8388608];   // combine out [4096][2048]
__device__ __nv_bfloat16 g_wh0[4194304], g_wl0[4194304]; // wq
__device__ __nv_bfloat16 g_wh1[4194304], g_wl1[4194304]; // wk
__device__ __nv_bfloat16 g_wh2[4194304], g_wl2[4194304]; // wv
__device__ __nv_bfloat16 g_wh3[4194304], g_wl3[4194304]; // wo

// ---------------------------------------------------------------------------
// Helpers (all base-ISA: ldmatrix sm_75+, bf16 mma.sync + cp.async sm_80+)
// ---------------------------------------------------------------------------
__device__ __forceinline__ uint32_t smem_u32(const void* p) {
    uint32_t a;
    asm("{ .reg .u64 t; cvta.to.shared.u64 t, %1; cvt.u32.u64 %0, t; }" : "=r"(a) : "l"(p));
    return a;
}
__device__ __forceinline__ uint32_t sw128(uint32_t off) { return off ^ ((off >> 3) & 0x70); }

#define LDSM4(r, addr) \
    asm volatile("ldmatrix.sync.aligned.m8n8.x4.shared.b16 {%0,%1,%2,%3}, [%4];" \
        : "=r"((r)[0]), "=r"((r)[1]), "=r"((r)[2]), "=r"((r)[3]) : "r"(addr))

#define MMA16816(c, a, b0, b1) \
    asm volatile("mma.sync.aligned.m16n8k16.row.col.f32.bf16.bf16.f32 " \
        "{%0,%1,%2,%3}, {%4,%5,%6,%7}, {%8,%9}, {%0,%1,%2,%3};" \
        : "+f"((c)[0]), "+f"((c)[1]), "+f"((c)[2]), "+f"((c)[3]) \
        : "r"((a)[0]), "r"((a)[1]), "r"((a)[2]), "r"((a)[3]), "r"(b0), "r"(b1))

#define CP16(dst, src) \
    asm volatile("cp.async.cg.shared.global [%0], [%1], 16;" :: "r"(dst), "l"(src))
#define CP_COMMIT() asm volatile("cp.async.commit_group;")
#define CP_WAIT1()  asm volatile("cp.async.wait_group 1;" ::: "memory")
#define CP_WAIT0()  asm volatile("cp.async.wait_group 0;" ::: "memory")

// ---------------------------------------------------------------------------
// fp32 -> bf16 hi/lo conversion.  sel: 0=x, 1=wq, 2=wk, 3=wv, 4=wo
// ---------------------------------------------------------------------------
__global__ __launch_bounds__(256) void convert_kernel(const float* __restrict__ src,
                                                      int sel, int n4)
{
    int i = blockIdx.x * 256 + threadIdx.x;
    if (i >= n4) return;
    __nv_bfloat16 *dh, *dl;
    switch (sel) {
        case 0: dh = g_xh;  dl = g_xl;  break;
        case 1: dh = g_wh0; dl = g_wl0; break;
        case 2: dh = g_wh1; dl = g_wl1; break;
        case 3: dh = g_wh2; dl = g_wl2; break;
        default: dh = g_wh3; dl = g_wl3; break;
    }
    float4 v = ((const float4*)src)[i];
    __nv_bfloat16 hx = __float2bfloat16(v.x);
    __nv_bfloat16 hy = __float2bfloat16(v.y);
    __nv_bfloat16 hz = __float2bfloat16(v.z);
    __nv_bfloat16 hw = __float2bfloat16(v.w);
    __nv_bfloat16 lx = __float2bfloat16(v.x - __bfloat162float(hx));
    __nv_bfloat16 ly = __float2bfloat16(v.y - __bfloat162float(hy));
    __nv_bfloat16 lz = __float2bfloat16(v.z - __bfloat162float(hz));
    __nv_bfloat16 lw = __float2bfloat16(v.w - __bfloat162float(hw));
    __nv_bfloat162 h01; h01.x = hx; h01.y = hy;
    __nv_bfloat162 h23; h23.x = hz; h23.y = hw;
    __nv_bfloat162 l01; l01.x = lx; l01.y = ly;
    __nv_bfloat162 l23; l23.x = lz; l23.y = lw;
    ((__nv_bfloat162*)dh)[i * 2]     = h01;
    ((__nv_bfloat162*)dh)[i * 2 + 1] = h23;
    ((__nv_bfloat162*)dl)[i * 2]     = l01;
    ((__nv_bfloat162*)dl)[i * 2 + 1] = l23;
}

// ---------------------------------------------------------------------------
// Tensor-core GEMM via mma.sync (bf16 hi/lo 3-pass, fp32 accumulate):
//   C[r][c] = sum_k A[r][k] * W[c][k]      M=4096, N=2048, K=2048
// 128x128 tile/CTA, BK=32, 256 thr (8 warps 2x4, each 64x32 out).
// cp.async 3-stage pipeline; smem rows 128B = [hi 64B | lo 64B], SW128.
// Pass-major MMA schedule: RAW reuse distance 4 (was 0).
// mode: 0 row-major Cout; 1 g_Q scatter; 2 g_K scatter; 3 g_V scatter.
// ---------------------------------------------------------------------------
__device__ __forceinline__ void epi_store2(int mode, float* __restrict__ Cout,
                                           int R, int C, float v0, float v1)
{
    float2 v = make_float2(v0, v1);
    if (mode == 0) {
        *(float2*)(Cout + (size_t)R * 2048 + C) = v;
    } else if (mode == 3) {
        int bb = R >> 11, s = R & 2047, hd = C >> 7, cc = C & 127;
        *(float2*)(g_V + ((size_t)(bb * 16 + hd) * 2048 + s) * 128 + cc) = v;
    } else {
        float* G = (mode == 1) ? g_Q : g_K;
        int bb = R >> 11, s = R & 2047, h2 = C >> 6, dd = C & 63;
        *(float2*)(G + ((size_t)(bb * 32 + h2) * 2048 + s) * 64 + dd) = v;
    }
}

__global__ __launch_bounds__(256, 2) void gemm_mma(int asel, int wsel, int mode,
                                                   float* __restrict__ Cout)
{
    extern __shared__ char dynsmem[];
    uint32_t sbase = (smem_u32(dynsmem) + 127) & ~127u;

    const int tid  = threadIdx.x;
    const int lane = tid & 31, wid = tid >> 5;
    const int wm = wid >> 2, wn = wid & 3;          // warp grid 2 x 4
    const int m0 = blockIdx.y * 128, n0 = blockIdx.x * 128;

    const __nv_bfloat16 *Ahp = asel ? g_Ah : g_xh;
    const __nv_bfloat16 *Alp = asel ? g_Al : g_xl;
    const __nv_bfloat16 *Bhp, *Blp;
    if      (wsel == 0) { Bhp = g_wh0; Blp = g_wl0; }
    else if (wsel == 1) { Bhp = g_wh1; Blp = g_wl1; }
    else if (wsel == 2) { Bhp = g_wh2; Blp = g_wl2; }
    else                { Bhp = g_wh3; Blp = g_wl3; }

    // per-thread copy geometry (fixed): i in 0..3 -> part = i>>1 (hi/lo),
    // row = (i&1)*64 + tid/4, 16B chunk j = tid&3
    const int ldrow_lo = tid >> 2;
    const int ldj = tid & 3;
    const __nv_bfloat16* asrc[4];
    const __nv_bfloat16* bsrc[4];
    uint32_t soff[4];
    #pragma unroll
    for (int i = 0; i < 4; i++) {
        int part = i >> 1, row = ((i & 1) << 6) + ldrow_lo;
        const __nv_bfloat16* As = part ? Alp : Ahp;
        const __nv_bfloat16* Bs = part ? Blp : Bhp;
        asrc[i] = As + (size_t)(m0 + row) * 2048 + ldj * 8;
        bsrc[i] = Bs + (size_t)(n0 + row) * 2048 + ldj * 8;
        soff[i] = sw128((uint32_t)(row * 128 + part * 64 + ldj * 16));
    }

    float cacc[4][4][4];
    #pragma unroll
    for (int mt = 0; mt < 4; mt++)
        #pragma unroll
        for (int nt = 0; nt < 4; nt++)
            #pragma unroll
            for (int q = 0; q < 4; q++) cacc[mt][nt][q] = 0.f;

    // prologue: stages 0,1 <- chunks 0,1
    #pragma unroll
    for (int c = 0; c < 2; c++) {
        uint32_t st = sbase + c * 32768;
        #pragma unroll
        for (int i = 0; i < 4; i++) {
            CP16(st + soff[i],         asrc[i] + c * 32);
            CP16(st + 16384 + soff[i], bsrc[i] + c * 32);
        }
        CP_COMMIT();
    }

    for (int chunk = 0; chunk < 64; chunk++) {
        if (chunk == 63) { CP_WAIT0(); } else { CP_WAIT1(); }
        __syncthreads();

        // issue chunk+2 into stage (chunk+2)%3 (freed by the barrier)
        if (chunk + 2 < 64) {
            int nc = chunk + 2;
            uint32_t st = sbase + (nc % 3) * 32768;
            #pragma unroll
            for (int i = 0; i < 4; i++) {
                CP16(st + soff[i],         asrc[i] + nc * 32);
                CP16(st + 16384 + soff[i], bsrc[i] + nc * 32);
            }
            CP_COMMIT();
        }

        uint32_t aB = sbase + (chunk % 3) * 32768;
        uint32_t bB = aB + 16384;

        #pragma unroll
        for (int ks = 0; ks < 2; ks++) {
            uint32_t colb = ks * 32 + ((lane >> 4) << 4);   // k-half select
            uint32_t bfh[2][4], bfl[2][4];
            #pragma unroll
            for (int np = 0; np < 2; np++) {
                uint32_t brow = (uint32_t)(wn * 32 + np * 16 + (lane & 15));
                uint32_t off = brow * 128 + colb;
                LDSM4(bfh[np], bB + sw128(off));
                LDSM4(bfl[np], bB + sw128(off + 64));
            }
            #pragma unroll
            for (int mt = 0; mt < 4; mt++) {
                uint32_t arow = (uint32_t)(wm * 64 + mt * 16 + (lane & 15));
                uint32_t off = arow * 128 + colb;
                uint32_t ah[4], al[4];
                LDSM4(ah, aB + sw128(off));
                LDSM4(al, aB + sw128(off + 64));
                // pass-major: per-accumulator op sequence unchanged (hh, hl, lh)
                // but RAW reuse distance is now 4 MMAs instead of 0.
                #pragma unroll
                for (int nt = 0; nt < 4; nt++) {
                    int np = nt >> 1, sel = nt & 1;
                    MMA16816(cacc[mt][nt], ah, bfh[np][sel], bfh[np][sel + 2]); // Ah*Bh
                }
                #pragma unroll
                for (int nt = 0; nt < 4; nt++) {
                    int np = nt >> 1, sel = nt & 1;
                    MMA16816(cacc[mt][nt], ah, bfl[np][sel], bfl[np][sel + 2]); // Ah*Bl
                }
                #pragma unroll
                for (int nt = 0; nt < 4; nt++) {
                    int np = nt >> 1, sel = nt & 1;
                    MMA16816(cacc[mt][nt], al, bfh[np][sel], bfh[np][sel + 2]); // Al*Bh
                }
            }
        }
        __syncthreads();
    }

    // epilogue: direct scatter from accumulators (float2 per store)
    #pragma unroll
    for (int mt = 0; mt < 4; mt++) {
        #pragma unroll
        for (int nt = 0; nt < 4; nt++) {
            int R = m0 + wm * 64 + mt * 16 + (lane >> 2);
            int C = n0 + wn * 32 + nt * 8 + ((lane & 3) << 1);
            epi_store2(mode, Cout, R,     C, cacc[mt][nt][0], cacc[mt][nt][1]);
            epi_store2(mode, Cout, R + 8, C, cacc[mt][nt][2], cacc[mt][nt][3]);
        }
    }
}

// ---------------------------------------------------------------------------
// RoPE in-place on g_Q/g_K
// ---------------------------------------------------------------------------
__global__ __launch_bounds__(256) void rope_kernel(const float* __restrict__ cosb,
                                                   const float* __restrict__ sinb)
{
    int idx = blockIdx.x * blockDim.x + threadIdx.x;
    const int total = 2 * 32 * 2048 * 32;
    if (idx >= total) return;
    int j = idx & 31;
    int s = (idx >> 5) & 2047;
    float c  = cosb[s * 32 + j];
    float sn = sinb[s * 32 + j];
    float2* q2 = (float2*)g_Q;
    float2* k2 = (float2*)g_K;
    float2 q = q2[idx];
    q2[idx] = make_float2(q.x * c - q.y * sn, q.x * sn + q.y * c);
    float2 k = k2[idx];
    k2[idx] = make_float2(k.x * c - k.y * sn, k.x * sn + k.y * c);
}

__global__ void lam_kernel(const float* __restrict__ lq1, const float* __restrict__ lk1,
                           const float* __restrict__ lq2, const float* __restrict__ lk2)
{
    if (threadIdx.x == 0) {
        float a = 0.f, b = 0.f;
        for (int i = 0; i < 64; i++) { a += lq1[i] * lk1[i]; b += lq2[i] * lk2[i]; }
        float li = 0.8f - 0.6f * expf(-9.6f);
        g_lam = expf(a) - expf(b) + li;
    }
}

// ---------------------------------------------------------------------------
// Causal flash attention (fp32) — unchanged from passing R12 kernel
// ---------------------------------------------------------------------------
__global__ __launch_bounds__(256) void attn_kernel()
{
    __shared__ __align__(16) float Qst[64 * 68];
    __shared__ __align__(16) float KstSs[64 * 36];
    __shared__ __align__(16) float Vs[32 * 128];
    __shared__ float mrow[64], lrow[64], arow[64];

    int tid = threadIdx.x;
    int unit = blockIdx.y;
    int b   = unit >> 5;
    int h   = (unit >> 1) & 15;
    int var = unit & 1;
    int q0  = blockIdx.x * 64;

    const float* Qg = g_Q + (size_t)(b * 32 + h * 2 + var) * 2048 * 64;
    const float* Kg = g_K + (size_t)(b * 32 + h * 2 + var) * 2048 * 64;
    const float* Vg = g_V + (size_t)(b * 16 + h) * 2048 * 128;
    float*       Og = g_O + (size_t)var * 8388608 + (size_t)(b * 16 + h) * 2048 * 128;

    #pragma unroll
    for (int t = 0; t < 16; t++) {
        int e = tid + t * 256;
        int i = e >> 6, d = e & 63;
        Qst[d * 68 + i] = Qg[(size_t)(q0 + i) * 64 + d];
    }
    if (tid < 64) { mrow[tid] = -1e30f; lrow[tid] = 0.f; }

    int ty = tid >> 4, tx = tid & 15;
    int rg = tid >> 4, cg = tid & 15;
    int srow = tid >> 2, part = tid & 3;

    float o[4][8];
    #pragma unroll
    for (int ii = 0; ii < 4; ii++)
        #pragma unroll
        for (int c = 0; c < 8; c++) o[ii][c] = 0.f;

    int nkt = (q0 >> 5) + 2;

    for (int kt = 0; kt < nkt; kt++) {
        __syncthreads();
        #pragma unroll
        for (int t = 0; t < 8; t++) {
            int e = tid + t * 256;
            int j = e >> 6, d = e & 63;
            KstSs[d * 36 + j] = Kg[(size_t)(kt * 32 + j) * 64 + d];
        }
        #pragma unroll
        for (int t = 0; t < 4; t++) {
            int e = tid + t * 256;
            int j = e >> 5, c4 = e & 31;
            *(float4*)&Vs[j * 128 + c4 * 4] =
                *(const float4*)&Vg[(size_t)(kt * 32 + j) * 128 + c4 * 4];
        }
        __syncthreads();

        float acc[4][2] = {};
        #pragma unroll 16
        for (int d = 0; d < 64; d++) {
            float4 a  = *(const float4*)&Qst[d * 68 + ty * 4];
            float2 bv = *(const float2*)&KstSs[d * 36 + tx * 2];
            acc[0][0] += a.x * bv.x; acc[0][1] += a.x * bv.y;
            acc[1][0] += a.y * bv.x; acc[1][1] += a.y * bv.y;
            acc[2][0] += a.z * bv.x; acc[2][1] += a.z * bv.y;
            acc[3][0] += a.w * bv.x; acc[3][1] += a.w * bv.y;
        }
        __syncthreads();

        bool needmask = (kt * 32 + 31) > q0;
        #pragma unroll
        for (int ii = 0; ii < 4; ii++) {
            int row = ty * 4 + ii;
            #pragma unroll
            for (int jj = 0; jj < 2; jj++) {
                int col = tx * 2 + jj;
                float sv = acc[ii][jj] * 0.125f;
                if (needmask && (kt * 32 + col > q0 + row)) sv = -1e30f;
                KstSs[row * 33 + col] = sv;
            }
        }
        __syncthreads();

        {
            float sv[8]; float mx = -1e30f;
            #pragma unroll
            for (int k2 = 0; k2 < 8; k2++) {
                sv[k2] = KstSs[srow * 33 + part * 8 + k2];
                mx = fmaxf(mx, sv[k2]);
            }
            mx = fmaxf(mx, __shfl_xor_sync(0xffffffffu, mx, 1));
            mx = fmaxf(mx, __shfl_xor_sync(0xffffffffu, mx, 2));
            float mold = mrow[srow];
            float mnew = fmaxf(mold, mx);
            float psum = 0.f;
            #pragma unroll
            for (int k2 = 0; k2 < 8; k2++) {
                float p = __expf(sv[k2] - mnew);
                KstSs[srow * 33 + part * 8 + k2] = p;
                psum += p;
            }
            psum += __shfl_xor_sync(0xffffffffu, psum, 1);
            psum += __shfl_xor_sync(0xffffffffu, psum, 2);
            if (part == 0) {
                float al = __expf(mold - mnew);
                arow[srow] = al;
                lrow[srow] = lrow[srow] * al + psum;
                mrow[srow] = mnew;
            }
        }
        __syncthreads();

        {
            float al[4];
            #pragma unroll
            for (int ii = 0; ii < 4; ii++) al[ii] = arow[rg * 4 + ii];
            #pragma unroll
            for (int ii = 0; ii < 4; ii++)
                #pragma unroll
                for (int c = 0; c < 8; c++) o[ii][c] *= al[ii];

            #pragma unroll 4
            for (int j = 0; j < 32; j++) {
                float4 v0 = *(const float4*)&Vs[j * 128 + cg * 8];
                float4 v1 = *(const float4*)&Vs[j * 128 + cg * 8 + 4];
                float vv[8] = {v0.x, v0.y, v0.z, v0.w, v1.x, v1.y, v1.z, v1.w};
                float pp[4];
                #pragma unroll
                for (int ii = 0; ii < 4; ii++) pp[ii] = KstSs[(rg * 4 + ii) * 33 + j];
                #pragma unroll
                for (int ii = 0; ii < 4; ii++)
                    #pragma unroll
                    for (int c = 0; c < 8; c++)
                        o[ii][c] += pp[ii] * vv[c];
            }
        }
    }

    #pragma unroll
    for (int ii = 0; ii < 4; ii++) {
        float linv = 1.0f / lrow[rg * 4 + ii];
        float4 r0 = make_float4(o[ii][0] * linv, o[ii][1] * linv,
                                o[ii][2] * linv, o[ii][3] * linv);
        float4 r1 = make_float4(o[ii][4] * linv, o[ii][5] * linv,
                                o[ii][6] * linv, o[ii][7] * linv);
        size_t base = (size_t)(q0 + rg * 4 + ii) * 128 + cg * 8;
        *(float4*)&Og[base]     = r0;
        *(float4*)&Og[base + 4] = r1;
    }
}

// ---------------------------------------------------------------------------
// Combine: attn = (O1 - lam*O2); RMSNorm(128); * subln_w * (1-LAMBDA_INIT)
// Emits bf16 hi/lo directly into g_Ah/g_Al (GEMM-ready row-major).
// ---------------------------------------------------------------------------
__global__ __launch_bounds__(256) void combine_kernel(const float* __restrict__ subw)
{
    int warp = threadIdx.x >> 5, lane = threadIdx.x & 31;
    int v = blockIdx.x * 8 + warp;        // (b*16+h)*2048 + s
    const float4* p1 = (const float4*)g_O + (size_t)v * 32;
    const float4* p2 = (const float4*)(g_O + 8388608) + (size_t)v * 32;

    float lam = g_lam;
    float4 x1 = p1[lane], x2 = p2[lane];
    float4 a = make_float4(x1.x - lam * x2.x, x1.y - lam * x2.y,
                           x1.z - lam * x2.z, x1.w - lam * x2.w);
    float ss = a.x * a.x + a.y * a.y + a.z * a.z + a.w * a.w;
    #pragma unroll
    for (int off = 16; off > 0; off >>= 1)
        ss += __shfl_xor_sync(0xffffffffu, ss, off);

    float li = 0.8f - 0.6f * expf(-9.6f);
    float sc = rsqrtf(ss * (1.0f / 128.0f) + 1e-5f) * (1.0f - li);
    float4 w = ((const float4*)subw)[lane];
    float4 out = make_float4(a.x * sc * w.x, a.y * sc * w.y,
                             a.z * sc * w.z, a.w * sc * w.w);

    int bb = v >> 15;
    int hh = (v >> 11) & 15;
    int s  = v & 2047;
    size_t base = (size_t)(bb * 2048 + s) * 2048 + hh * 128 + lane * 4;

    __nv_bfloat16 h0 = __float2bfloat16(out.x);
    __nv_bfloat16 h1 = __float2bfloat16(out.y);
    __nv_bfloat16 h2 = __float2bfloat16(out.z);
    __nv_bfloat16 h3 = __float2bfloat16(out.w);
    __nv_bfloat16 l0 = __float2bfloat16(out.x - __bfloat162float(h0));
    __nv_bfloat16 l1 = __float2bfloat16(out.y - __bfloat162float(h1));
    __nv_bfloat16 l2 = __float2bfloat16(out.z - __bfloat162float(h2));
    __nv_bfloat16 l3 = __float2bfloat16(out.w - __bfloat162float(h3));
    __nv_bfloat162 ha; ha.x = h0; ha.y = h1;
    __nv_bfloat162 hb; hb.x = h2; hb.y = h3;
    __nv_bfloat162 la; la.x = l0; la.y = l1;
    __nv_bfloat162 lb; lb.x = l2; lb.y = l3;
    ((__nv_bfloat162*)(g_Ah + base))[0] = ha;
    ((__nv_bfloat162*)(g_Ah + base))[1] = hb;
    ((__nv_bfloat162*)(g_Al + base))[0] = la;
    ((__nv_bfloat162*)(g_Al + base))[1] = lb;
}

// ---------------------------------------------------------------------------
extern "C" void kernel_launch(void* const* d_in, const int* in_sizes, int n_in,
                              void* d_out, int out_size)
{
    const float* x    = (const float*)d_in[0];
    const float* wq   = (const float*)d_in[1];
    const float* wk   = (const float*)d_in[2];
    const float* wv   = (const float*)d_in[3];
    const float* wo   = (const float*)d_in[4];
    const float* lq1  = (const float*)d_in[5];
    const float* lk1  = (const float*)d_in[6];
    const float* lq2  = (const float*)d_in[7];
    const float* lk2  = (const float*)d_in[8];
    const float* subw = (const float*)d_in[9];
    const float* rc   = (const float*)d_in[10];
    const float* rs   = (const float*)d_in[11];

    const int SMEM_BYTES = 3 * 32768 + 128;   // 3-stage pipeline
    static int attr_set = 0;
    if (!attr_set) {
        cudaFuncSetAttribute(gemm_mma, cudaFuncAttributeMaxDynamicSharedMemorySize, SMEM_BYTES);
        attr_set = 1;
    }

    dim3 gemm_grid(16, 32), gemm_blk(256);

    // Order chosen so gemm_mma lands at launch index 3 (ncu capture slot).
    convert_kernel<<<8192, 256>>>(x,  0, 2097152);                     // 0
    convert_kernel<<<4096, 256>>>(wq, 1, 1048576);                     // 1
    convert_kernel<<<4096, 256>>>(wk, 2, 1048576);                     // 2
    gemm_mma<<<gemm_grid, gemm_blk, SMEM_BYTES>>>(0, 0, 1, nullptr);   // 3: Q (profiled)
    gemm_mma<<<gemm_grid, gemm_blk, SMEM_BYTES>>>(0, 1, 2, nullptr);   // 4: K
    convert_kernel<<<4096, 256>>>(wv, 3, 1048576);                     // 5
    gemm_mma<<<gemm_grid, gemm_blk, SMEM_BYTES>>>(0, 2, 3, nullptr);   // 6: V
    convert_kernel<<<4096, 256>>>(wo, 4, 1048576);                     // 7

    rope_kernel<<<16384, 256>>>(rc, rs);
    lam_kernel<<<1, 32>>>(lq1, lk1, lq2, lk2);
    attn_kernel<<<dim3(32, 64), 256>>>();
    combine_kernel<<<8192, 256>>>(subw);

    gemm_mma<<<gemm_grid, gemm_blk, SMEM_BYTES>>>(1, 3, 0, (float*)d_out);  // out proj
}